// round 4
// baseline (speedup 1.0000x reference)
#include <cuda_runtime.h>

// DistMaps: out[b,g,r,c] = tanh(2*sqrt(min_p d2)) over 24 clicks per (b,g) group,
// d2 = ((r-pr)/5)^2 + ((c-pc)/5)^2, invalid clicks (max coords < 0) -> 1e6.
// x input (d_in[0]) is shape-only; output depends only on coords (d_in[1]).
//
// R4: two-phase. Pixels farther than sqrt(41)*5 = 32.02 px from every valid
// click produce exactly tanhf(>=12.8) == 1.0f. So:
//   kernel 1: fill the whole output with 1.0f (pure streaming stores).
//   kernel 2: one block per (click, group) rewrites a 68x72 box around the
//             click with the true value (min over clicks relevant to the box).
// Box-culled click set contains every click within 32.03px of ANY box pixel,
// so each box computes the exact (clamped-at-41) min; overlapping boxes write
// identical values -> benign duplicate writes, no atomics needed.

namespace {

constexpr int   H         = 512;
constexpr int   W         = 512;
constexpr int   P         = 24;      // clicks per group
constexpr float INV_SCALE = 0.2f;    // 1 / (NORM_RADIUS * SPATIAL_SCALE)
// d2 >= 41  =>  2*sqrt(d2) >= 12.8  =>  tanh rounds to exactly 1.0f.
constexpr float CULL_D2   = 41.0f;

constexpr int PROWS = 68;            // patch rows  (covers radius 32.03 + slack)
constexpr int PCOLS = 72;            // patch cols  (float4-aligned)
constexpr int PQ    = PCOLS / 4;     // 18 float4 per patch row
constexpr int PQUADS = PROWS * PQ;   // 1224

__device__ __forceinline__ float tanh_2sqrt_fast(float q) {
    float s, t;
    asm("sqrt.approx.f32 %0, %1;" : "=f"(s) : "f"(q));
    s = 2.0f * s;
    asm("tanh.approx.f32 %0, %1;" : "=f"(t) : "f"(s));
    return t;
}

__global__ __launch_bounds__(256) void fill_kernel(float4* __restrict__ out, int n4) {
    const float4 ones = make_float4(1.0f, 1.0f, 1.0f, 1.0f);
    int i = blockIdx.x * 256 + threadIdx.x;
    const int stride = gridDim.x * 256;
    for (; i < n4; i += stride) out[i] = ones;
}

__global__ __launch_bounds__(256) void patch_kernel(
    const float* __restrict__ coords,   // [B, 48, 3] (row, col, _)
    float*       __restrict__ out)      // [B, 2, H, W]
{
    __shared__ float s_prs[P];
    __shared__ float s_pcs[P];
    __shared__ int   s_n;

    const int pk  = blockIdx.x;      // click index within group, 0..23
    const int bg  = blockIdx.y;      // 0..2B-1
    const int tid = threadIdx.x;

    // Center click of this patch (broadcast load, all threads same address).
    const float* cp = coords + (size_t)(bg * P + pk) * 3;
    const float pr = __ldg(cp);
    const float pc = __ldg(cp + 1);
    if (fmaxf(pr, pc) < 0.0f) return;   // invalid click: fill value stands

    // Patch box (clamped to image, column base float4-aligned).
    int row_lo = (int)floorf(pr) - 33;
    row_lo = max(0, min(row_lo, H - PROWS));
    int col_lo = ((int)floorf(pc) - 34) & ~3;
    col_lo = max(0, min(col_lo, W - PCOLS));

    // Warp 0: keep clicks whose scaled rect-distance^2 to the box is < 41.
    if (tid < 32) {
        bool  near = false;
        float prs = 0.0f, pcs = 0.0f;
        if (tid < P) {
            const float* cq = coords + (size_t)(bg * P + tid) * 3;
            float qr = cq[0];
            float qc = cq[1];
            bool valid = fmaxf(qr, qc) >= 0.0f;
            float rr = fminf(fmaxf(qr, (float)row_lo), (float)(row_lo + PROWS - 1));
            float cc = fminf(fmaxf(qc, (float)col_lo), (float)(col_lo + PCOLS - 1));
            float dr = (rr - qr) * INV_SCALE;
            float dc = (cc - qc) * INV_SCALE;
            near = valid && (fmaf(dr, dr, dc * dc) < CULL_D2);
            prs = qr * INV_SCALE;
            pcs = qc * INV_SCALE;
        }
        unsigned mask = __ballot_sync(0xffffffffu, near);
        if (near) {
            int pos = __popc(mask & ((1u << tid) - 1u));
            s_prs[pos] = prs;
            s_pcs[pos] = pcs;
        }
        if (tid == 0) s_n = __popc(mask);
    }
    __syncthreads();

    const int n = s_n;   // >= 1 (the center click always survives)
    float* __restrict__ obase = out + (size_t)bg * H * W;

    for (int qi = tid; qi < PQUADS; qi += 256) {
        const int r   = qi / PQ;          // const divisor -> mul/shift
        const int c4  = qi - r * PQ;
        const int row = row_lo + r;
        const int col = col_lo + c4 * 4;

        const float rs = (float)row * INV_SCALE;
        const float a0 = (float)(col + 0) * INV_SCALE;
        const float a1 = (float)(col + 1) * INV_SCALE;
        const float a2 = (float)(col + 2) * INV_SCALE;
        const float a3 = (float)(col + 3) * INV_SCALE;

        float q0 = CULL_D2, q1 = CULL_D2, q2 = CULL_D2, q3 = CULL_D2;

        for (int p = 0; p < n; ++p) {
            const float dr = rs - s_prs[p];
            const float e  = dr * dr;
            const float pcs = s_pcs[p];
            float d;
            d = a0 - pcs; q0 = fminf(q0, fmaf(d, d, e));
            d = a1 - pcs; q1 = fminf(q1, fmaf(d, d, e));
            d = a2 - pcs; q2 = fminf(q2, fmaf(d, d, e));
            d = a3 - pcs; q3 = fminf(q3, fmaf(d, d, e));
        }

        float4 v;
        v.x = tanh_2sqrt_fast(q0);
        v.y = tanh_2sqrt_fast(q1);
        v.z = tanh_2sqrt_fast(q2);
        v.w = tanh_2sqrt_fast(q3);
        *reinterpret_cast<float4*>(obase + (size_t)row * W + col) = v;
    }
}

}  // namespace

extern "C" void kernel_launch(void* const* d_in, const int* in_sizes, int n_in,
                              void* d_out, int out_size) {
    // d_in[0]: x [B,3,512,512] f32 (unused), d_in[1]: coords [B,48,3] f32
    const float* coords = (const float*)d_in[1];
    float* out = (float*)d_out;

    const int B  = in_sizes[1] / (48 * 3);   // 8
    const int n4 = out_size / 4;

    fill_kernel<<<1024, 256>>>(reinterpret_cast<float4*>(out), n4);

    dim3 grid(P, B * 2);
    patch_kernel<<<grid, 256>>>(coords, out);
}